// round 1
// baseline (speedup 1.0000x reference)
#include <cuda_runtime.h>

#define BATCH 256
#define LSEQ  196
#define DIM   2048
#define ATT   512
#define NROWS (BATCH * LSEQ)   // 50176 = 64 * 784 exactly

// Scratch (no allocations allowed)
__device__ float g_c[BATCH * ATT];       // att2 + b_dec + b_enc, per (n, a)
__device__ float g_scores[NROWS];        // pre-softmax scores, init to b_tot

// ---------------------------------------------------------------------------
// Kernel 1: c[n,a] = b_enc[a] + b_dec[a] + sum_h prev_h[n,h] * W_dec[h,a]
//           also initializes g_scores to b_tot[0]
// grid: BATCH blocks, 512 threads
// ---------------------------------------------------------------------------
__global__ void k_compute_c(const float* __restrict__ prev_h,
                            const float* __restrict__ W_dec,
                            const float* __restrict__ b_enc,
                            const float* __restrict__ b_dec,
                            const float* __restrict__ b_tot) {
    __shared__ float sh[ATT];            // N_HID == 512
    int n = blockIdx.x;
    int a = threadIdx.x;
    sh[a] = prev_h[n * ATT + a];
    __syncthreads();

    float acc = b_enc[a] + b_dec[a];
#pragma unroll 8
    for (int h = 0; h < ATT; h++) {
        acc = fmaf(sh[h], W_dec[h * ATT + a], acc);
    }
    g_c[n * ATT + a] = acc;

    // init scores (131072 threads total, 50176 entries)
    int gid = n * ATT + a;
    if (gid < NROWS) g_scores[gid] = b_tot[0];
}

// ---------------------------------------------------------------------------
// Kernel 2: big GEMM  att1[row, a] = feature[row,:] @ W_enc[:, a]
//           fused: score_partial[row] += sum_a relu(att1 + c[n,a]) * W_tot[a]
// Tile: BM=64 rows x BN=128 atts x BK=16, 256 threads, 4x8 accum per thread.
// grid: (NROWS/64, ATT/128) = (784, 4)
// ---------------------------------------------------------------------------
#define BM 64
#define BN 128
#define BK 16

__global__ void __launch_bounds__(256)
k_scores(const float* __restrict__ feature,
         const float* __restrict__ W_enc,
         const float* __restrict__ W_tot) {
    __shared__ float As[BK][BM];
    __shared__ float Bs[BK][BN];

    const int rowTile = blockIdx.x * BM;
    const int aTile   = blockIdx.y * BN;
    const int tid = threadIdx.x;
    const int tr  = tid >> 4;            // 0..15 thread-row
    const int tc  = tid & 15;            // 0..15 thread-col

    // load mappings
    const int ar = tid >> 2;             // 0..63  A row within tile
    const int ak = (tid & 3) << 2;       // 0,4,8,12 A k offset (float4)
    const int bk = tid >> 4;             // 0..15  B k row
    const int bc = (tid & 15) << 2;      // 0..60  B col offset (float4)

    const float* Aptr = feature + (size_t)(rowTile + ar) * DIM;
    const float* Bptr = W_enc + (size_t)bk * ATT + aTile;

    float acc[4][8];
#pragma unroll
    for (int i = 0; i < 4; i++)
#pragma unroll
        for (int j = 0; j < 8; j++) acc[i][j] = 0.f;

    for (int k0 = 0; k0 < DIM; k0 += BK) {
        // A: 64x16 floats, transposed into As[k][row]
        float4 av = *(const float4*)(Aptr + k0 + ak);
        As[ak + 0][ar] = av.x;
        As[ak + 1][ar] = av.y;
        As[ak + 2][ar] = av.z;
        As[ak + 3][ar] = av.w;
        // B: 16x128 floats
        float4 bv0 = *(const float4*)(Bptr + (size_t)k0 * ATT + bc);
        float4 bv1 = *(const float4*)(Bptr + (size_t)k0 * ATT + bc + 64);
        *(float4*)&Bs[bk][bc]      = bv0;
        *(float4*)&Bs[bk][bc + 64] = bv1;
        __syncthreads();

#pragma unroll
        for (int kk = 0; kk < BK; kk++) {
            float a0 = As[kk][tr * 4 + 0];
            float a1 = As[kk][tr * 4 + 1];
            float a2 = As[kk][tr * 4 + 2];
            float a3 = As[kk][tr * 4 + 3];
            float4 bL = *(const float4*)&Bs[kk][tc * 8];
            float4 bH = *(const float4*)&Bs[kk][tc * 8 + 4];
            float b[8] = {bL.x, bL.y, bL.z, bL.w, bH.x, bH.y, bH.z, bH.w};
#pragma unroll
            for (int j = 0; j < 8; j++) {
                acc[0][j] = fmaf(a0, b[j], acc[0][j]);
                acc[1][j] = fmaf(a1, b[j], acc[1][j]);
                acc[2][j] = fmaf(a2, b[j], acc[2][j]);
                acc[3][j] = fmaf(a3, b[j], acc[3][j]);
            }
        }
        __syncthreads();
    }

    // Epilogue: relu(+c) dot W_tot slice, atomic into scores
    float wt[8];
#pragma unroll
    for (int j = 0; j < 8; j++) wt[j] = W_tot[aTile + tc * 8 + j];

#pragma unroll
    for (int i = 0; i < 4; i++) {
        int row = rowTile + tr * 4 + i;
        int n = row / LSEQ;
        const float* crow = &g_c[n * ATT + aTile + tc * 8];
        float s = 0.f;
#pragma unroll
        for (int j = 0; j < 8; j++) {
            float v = acc[i][j] + crow[j];
            v = fmaxf(v, 0.f);
            s = fmaf(v, wt[j], s);
        }
        atomicAdd(&g_scores[row], s);
    }
}

// ---------------------------------------------------------------------------
// Kernel 3: softmax over L per batch. grid: BATCH blocks, 256 threads.
// writes alpha into d_out alpha region.
// ---------------------------------------------------------------------------
__global__ void k_softmax(float* __restrict__ alpha_out) {
    __shared__ float red[256];
    int n = blockIdx.x;
    int t = threadIdx.x;

    float v = (t < LSEQ) ? g_scores[n * LSEQ + t] : -1e30f;

    // max reduce
    red[t] = v;
    __syncthreads();
    for (int s = 128; s > 0; s >>= 1) {
        if (t < s) red[t] = fmaxf(red[t], red[t + s]);
        __syncthreads();
    }
    float vmax = red[0];
    __syncthreads();

    float e = (t < LSEQ) ? __expf(v - vmax) : 0.f;
    red[t] = e;
    __syncthreads();
    for (int s = 128; s > 0; s >>= 1) {
        if (t < s) red[t] += red[t + s];
        __syncthreads();
    }
    float inv = 1.f / red[0];

    if (t < LSEQ) alpha_out[n * LSEQ + t] = e * inv;
}

// ---------------------------------------------------------------------------
// Kernel 4: weighted_feature[n,d] = sum_l alpha[n,l] * feature[n,l,d]
// grid: (BATCH, 2), 256 threads, float4 per thread per half.
// ---------------------------------------------------------------------------
__global__ void k_weighted(const float* __restrict__ feature,
                           const float* __restrict__ alpha,
                           float* __restrict__ out) {
    __shared__ float sa[LSEQ];
    int n = blockIdx.x;
    int half = blockIdx.y;
    int t = threadIdx.x;
    if (t < LSEQ) sa[t] = alpha[n * LSEQ + t];
    __syncthreads();

    const float4* f = (const float4*)(feature + (size_t)n * LSEQ * DIM)
                      + half * 256 + t;
    float4 acc = make_float4(0.f, 0.f, 0.f, 0.f);
#pragma unroll 4
    for (int l = 0; l < LSEQ; l++) {
        float4 v = f[(size_t)l * (DIM / 4)];
        float al = sa[l];
        acc.x = fmaf(al, v.x, acc.x);
        acc.y = fmaf(al, v.y, acc.y);
        acc.z = fmaf(al, v.z, acc.z);
        acc.w = fmaf(al, v.w, acc.w);
    }
    ((float4*)(out + (size_t)n * DIM))[half * 256 + t] = acc;
}

// ---------------------------------------------------------------------------
extern "C" void kernel_launch(void* const* d_in, const int* in_sizes, int n_in,
                              void* d_out, int out_size) {
    const float* feature = (const float*)d_in[0];
    const float* prev_h  = (const float*)d_in[1];
    const float* W_enc   = (const float*)d_in[2];
    const float* b_enc   = (const float*)d_in[3];
    const float* W_dec   = (const float*)d_in[4];
    const float* b_dec   = (const float*)d_in[5];
    const float* W_tot   = (const float*)d_in[6];
    const float* b_tot   = (const float*)d_in[7];

    float* out   = (float*)d_out;
    float* wf    = out;                      // (BATCH, DIM)
    float* alpha = out + (size_t)BATCH * DIM; // (BATCH, LSEQ)

    k_compute_c<<<BATCH, 512>>>(prev_h, W_dec, b_enc, b_dec, b_tot);
    k_scores<<<dim3(NROWS / BM, ATT / BN), 256>>>(feature, W_enc, W_tot);
    k_softmax<<<BATCH, 256>>>(alpha);
    k_weighted<<<dim3(BATCH, 2), 256>>>(feature, alpha, wf);
}

// round 2
// speedup vs baseline: 2.7854x; 2.7854x over previous
#include <cuda_runtime.h>
#include <cstdint>

#define BATCH 256
#define LSEQ  196
#define DIM   2048
#define ATT   512
#define NROWS (BATCH * LSEQ)   // 50176 = 784 * 64

// GEMM tiling
#define BM 64
#define BK 8
#define GTHREADS 512           // 16 warps, warp tile 64x32
#define ASTRIDE 12             // BK + 4 pad (conflict-free frag reads)
#define BSTRIDE 520            // ATT + 8 pad (520 % 32 == 8 -> conflict-free)
#define NITER (DIM / BK)       // 256

// Scratch (no allocations allowed)
__device__ float g_c[BATCH * ATT];    // prev_h@W_dec + b_dec + b_enc
__device__ float g_scores[NROWS];     // pre-softmax scores

// ---------------------------------------------------------------------------
__device__ __forceinline__ uint32_t f2tf32(float x) {
    uint32_t u;
    asm("cvt.rna.tf32.f32 %0, %1;" : "=r"(u) : "f"(x));
    return u;
}

__device__ __forceinline__ void mma8(float* c, const uint32_t* a, const uint32_t* b) {
    asm volatile(
        "mma.sync.aligned.m16n8k8.row.col.f32.tf32.tf32.f32 "
        "{%0,%1,%2,%3}, {%4,%5,%6,%7}, {%8,%9}, {%0,%1,%2,%3};\n"
        : "+f"(c[0]), "+f"(c[1]), "+f"(c[2]), "+f"(c[3])
        : "r"(a[0]), "r"(a[1]), "r"(a[2]), "r"(a[3]),
          "r"(b[0]), "r"(b[1]));
}

// ---------------------------------------------------------------------------
// Kernel 1: c[n,a] = b_enc[a] + b_dec[a] + sum_h prev_h[n,h] * W_dec[h,a]
// ---------------------------------------------------------------------------
__global__ void k_compute_c(const float* __restrict__ prev_h,
                            const float* __restrict__ W_dec,
                            const float* __restrict__ b_enc,
                            const float* __restrict__ b_dec) {
    __shared__ float sh[ATT];
    int n = blockIdx.x;
    int a = threadIdx.x;
    sh[a] = prev_h[n * ATT + a];
    __syncthreads();

    float acc = b_enc[a] + b_dec[a];
#pragma unroll 8
    for (int h = 0; h < ATT; h++)
        acc = fmaf(sh[h], W_dec[h * ATT + a], acc);
    g_c[n * ATT + a] = acc;
}

// ---------------------------------------------------------------------------
// Kernel 2: tensor-core GEMM  att1[row, a] = feature[row,:] @ W_enc[:, a]
// fused epilogue: scores[row] = sum_a relu(att1 + c[n(row), a]) * W_tot[a]
// Block covers 64 rows x ALL 512 att cols -> full score reduced in-block.
// ---------------------------------------------------------------------------
__global__ void __launch_bounds__(GTHREADS, 1)
k_scores_tc(const float* __restrict__ feature,
            const float* __restrict__ W_enc,
            const float* __restrict__ W_tot) {
    __shared__ uint32_t As[2][BM][ASTRIDE];
    __shared__ uint32_t Bs[2][BK][BSTRIDE];
    __shared__ float cs[2][ATT];
    __shared__ float ssum[BM];

    const int t    = threadIdx.x;
    const int rowTile = blockIdx.x * BM;
    const int warp = t >> 5;
    const int lane = t & 31;
    const int g    = lane >> 2;   // groupID (0..7)
    const int tig  = lane & 3;    // thread in group (0..3)

    // c tiles for the (at most 2) batches this row-tile spans
    int n0 = rowTile / LSEQ;
    int n1 = n0 + 1; if (n1 > BATCH - 1) n1 = BATCH - 1;
    cs[0][t] = g_c[n0 * ATT + t];
    cs[1][t] = g_c[n1 * ATT + t];
    if (t < BM) ssum[t] = 0.f;
    const int n1row = (n0 + 1) * LSEQ;

    // A global mapping: threads 0..127 load 64x8 tile (1 float4 each)
    const int ar  = t >> 1;        // row 0..63 (valid for t<128)
    const int ac4 = t & 1;         // float4 col 0..1
    const float4* Agp = (const float4*)(feature + (size_t)(rowTile + ar) * DIM) + ac4;
    // B global mapping: 8x512 tile, 512 threads x 2 float4
    const int bk_ = t >> 6;        // k row 0..7
    const int bc4 = t & 63;        // float4 col 0..63 (+64 for second)

    float4 apf;
    float4 bpf[2];

    // ---- load iteration 0 into buffer 0 ----
    if (t < 128) apf = Agp[0];
    {
        const float4* Bgp = (const float4*)(W_enc + (size_t)bk_ * ATT) + bc4;
        bpf[0] = Bgp[0];
        bpf[1] = Bgp[64];
    }
    if (t < 128) {
        uint32_t* dst = &As[0][ar][ac4 * 4];
        dst[0] = f2tf32(apf.x); dst[1] = f2tf32(apf.y);
        dst[2] = f2tf32(apf.z); dst[3] = f2tf32(apf.w);
    }
#pragma unroll
    for (int j = 0; j < 2; j++) {
        uint32_t* dst = &Bs[0][bk_][(bc4 + j * 64) * 4];
        dst[0] = f2tf32(bpf[j].x); dst[1] = f2tf32(bpf[j].y);
        dst[2] = f2tf32(bpf[j].z); dst[3] = f2tf32(bpf[j].w);
    }
    __syncthreads();

    float acc[4][4][4];
#pragma unroll
    for (int mt = 0; mt < 4; mt++)
#pragma unroll
        for (int nt = 0; nt < 4; nt++)
#pragma unroll
            for (int r = 0; r < 4; r++) acc[mt][nt][r] = 0.f;

    for (int it = 0; it < NITER; ++it) {
        const int buf = it & 1;
        // prefetch next tile into registers
        if (it + 1 < NITER) {
            if (t < 128) apf = Agp[(it + 1) * 2];
            const float4* Bgp =
                (const float4*)(W_enc + (size_t)((it + 1) * BK + bk_) * ATT) + bc4;
            bpf[0] = Bgp[0];
            bpf[1] = Bgp[64];
        }

        // compute on current buffer (one k8 step)
        uint32_t af[4][4];
#pragma unroll
        for (int mt = 0; mt < 4; mt++) {
            int r = mt * 16 + g;
            af[mt][0] = As[buf][r    ][tig];
            af[mt][1] = As[buf][r + 8][tig];
            af[mt][2] = As[buf][r    ][tig + 4];
            af[mt][3] = As[buf][r + 8][tig + 4];
        }
        uint32_t bf[4][2];
#pragma unroll
        for (int nt = 0; nt < 4; nt++) {
            int col = warp * 32 + nt * 8 + g;
            bf[nt][0] = Bs[buf][tig    ][col];
            bf[nt][1] = Bs[buf][tig + 4][col];
        }
#pragma unroll
        for (int mt = 0; mt < 4; mt++)
#pragma unroll
            for (int nt = 0; nt < 4; nt++)
                mma8(acc[mt][nt], af[mt], bf[nt]);

        __syncthreads();
        if (it + 1 < NITER) {
            const int nb = (it + 1) & 1;
            if (t < 128) {
                uint32_t* dst = &As[nb][ar][ac4 * 4];
                dst[0] = f2tf32(apf.x); dst[1] = f2tf32(apf.y);
                dst[2] = f2tf32(apf.z); dst[3] = f2tf32(apf.w);
            }
#pragma unroll
            for (int j = 0; j < 2; j++) {
                uint32_t* dst = &Bs[nb][bk_][(bc4 + j * 64) * 4];
                dst[0] = f2tf32(bpf[j].x); dst[1] = f2tf32(bpf[j].y);
                dst[2] = f2tf32(bpf[j].z); dst[3] = f2tf32(bpf[j].w);
            }
            __syncthreads();
        }
    }

    // ---- fused epilogue: relu(+c) dot W_tot, reduce over all 512 cols ----
    float2 wt[4];
#pragma unroll
    for (int nt = 0; nt < 4; nt++) {
        int col = warp * 32 + nt * 8 + tig * 2;
        wt[nt].x = W_tot[col];
        wt[nt].y = W_tot[col + 1];
    }

#pragma unroll
    for (int mt = 0; mt < 4; mt++) {
        float rs0 = 0.f, rs1 = 0.f;
        int row0 = rowTile + mt * 16 + g;
        int row1 = row0 + 8;
        int s0 = (row0 >= n1row) ? 1 : 0;
        int s1 = (row1 >= n1row) ? 1 : 0;
#pragma unroll
        for (int nt = 0; nt < 4; nt++) {
            int col = warp * 32 + nt * 8 + tig * 2;
            float c00 = cs[s0][col], c01 = cs[s0][col + 1];
            float c10 = cs[s1][col], c11 = cs[s1][col + 1];
            rs0 += fmaxf(acc[mt][nt][0] + c00, 0.f) * wt[nt].x
                 + fmaxf(acc[mt][nt][1] + c01, 0.f) * wt[nt].y;
            rs1 += fmaxf(acc[mt][nt][2] + c10, 0.f) * wt[nt].x
                 + fmaxf(acc[mt][nt][3] + c11, 0.f) * wt[nt].y;
        }
        rs0 += __shfl_xor_sync(0xffffffff, rs0, 1);
        rs0 += __shfl_xor_sync(0xffffffff, rs0, 2);
        rs1 += __shfl_xor_sync(0xffffffff, rs1, 1);
        rs1 += __shfl_xor_sync(0xffffffff, rs1, 2);
        if (tig == 0) {
            atomicAdd(&ssum[mt * 16 + g], rs0);
            atomicAdd(&ssum[mt * 16 + g + 8], rs1);
        }
    }
    __syncthreads();
    if (t < BM) g_scores[rowTile + t] = ssum[t];
}

// ---------------------------------------------------------------------------
// Kernel 3: softmax over L per batch (b_tot omitted: softmax shift-invariant)
// ---------------------------------------------------------------------------
__global__ void k_softmax(float* __restrict__ alpha_out) {
    __shared__ float red[256];
    int n = blockIdx.x;
    int t = threadIdx.x;

    float v = (t < LSEQ) ? g_scores[n * LSEQ + t] : -1e30f;
    red[t] = v;
    __syncthreads();
    for (int s = 128; s > 0; s >>= 1) {
        if (t < s) red[t] = fmaxf(red[t], red[t + s]);
        __syncthreads();
    }
    float vmax = red[0];
    __syncthreads();

    float e = (t < LSEQ) ? __expf(v - vmax) : 0.f;
    red[t] = e;
    __syncthreads();
    for (int s = 128; s > 0; s >>= 1) {
        if (t < s) red[t] += red[t + s];
        __syncthreads();
    }
    float inv = 1.f / red[0];

    if (t < LSEQ) alpha_out[n * LSEQ + t] = e * inv;
}

// ---------------------------------------------------------------------------
// Kernel 4: weighted_feature[n,d] = sum_l alpha[n,l] * feature[n,l,d]
// ---------------------------------------------------------------------------
__global__ void k_weighted(const float* __restrict__ feature,
                           const float* __restrict__ alpha,
                           float* __restrict__ out) {
    __shared__ float sa[LSEQ];
    int n = blockIdx.x;
    int half = blockIdx.y;
    int t = threadIdx.x;
    if (t < LSEQ) sa[t] = alpha[n * LSEQ + t];
    __syncthreads();

    const float4* f = (const float4*)(feature + (size_t)n * LSEQ * DIM)
                      + half * 256 + t;
    float4 acc = make_float4(0.f, 0.f, 0.f, 0.f);
#pragma unroll 8
    for (int l = 0; l < LSEQ; l++) {
        float4 v = f[(size_t)l * (DIM / 4)];
        float al = sa[l];
        acc.x = fmaf(al, v.x, acc.x);
        acc.y = fmaf(al, v.y, acc.y);
        acc.z = fmaf(al, v.z, acc.z);
        acc.w = fmaf(al, v.w, acc.w);
    }
    ((float4*)(out + (size_t)n * DIM))[half * 256 + t] = acc;
}

// ---------------------------------------------------------------------------
extern "C" void kernel_launch(void* const* d_in, const int* in_sizes, int n_in,
                              void* d_out, int out_size) {
    const float* feature = (const float*)d_in[0];
    const float* prev_h  = (const float*)d_in[1];
    const float* W_enc   = (const float*)d_in[2];
    const float* b_enc   = (const float*)d_in[3];
    const float* W_dec   = (const float*)d_in[4];
    const float* b_dec   = (const float*)d_in[5];
    const float* W_tot   = (const float*)d_in[6];
    // d_in[7] = b_tot: softmax is shift-invariant -> unused

    float* out   = (float*)d_out;
    float* wf    = out;                        // (BATCH, DIM)
    float* alpha = out + (size_t)BATCH * DIM;  // (BATCH, LSEQ)

    k_compute_c<<<BATCH, 512>>>(prev_h, W_dec, b_enc, b_dec);
    k_scores_tc<<<NROWS / BM, GTHREADS>>>(feature, W_enc, W_tot);
    k_softmax<<<BATCH, 256>>>(alpha);
    k_weighted<<<dim3(BATCH, 2), 256>>>(feature, alpha, wf);
}

// round 4
// speedup vs baseline: 4.6857x; 1.6822x over previous
#include <cuda_runtime.h>
#include <cstdint>

#define BATCH 256
#define LSEQ  196
#define DIM   2048
#define ATT   512
#define NROWS (BATCH * LSEQ)   // 50176 = 392 * 128

// GEMM tiling
#define BM 128
#define BN 256
#define BK 32
#define NIT (DIM / BK)         // 64
#define THREADS 256            // 8 warps: 2 (m) x 4 (n), warp tile 64x64

#define A_STRIDE 36            // floats per A row (32 + 4 pad)
#define B_STRIDE 264           // floats per B k-row (256 + 8 pad)
#define A_STAGE (BM * A_STRIDE * 4)   // 18432 B
#define B_STAGE (BK * B_STRIDE * 4)   // 33792 B
#define OFF_SA 0u
#define OFF_SB (3u * A_STAGE)                 // 55296
#define OFF_CS (OFF_SB + 3u * B_STAGE)        // 156672  float[2][BN]
#define OFF_WT (OFF_CS + 2u * BN * 4u)        // 158720  float[BN]
#define SMEM_BYTES (OFF_WT + BN * 4u + 256u)  // ~160 KB

// Scratch globals (no allocation allowed)
__device__ float g_Wenc_r[DIM * ATT];  // W_enc rounded to tf32 (RNA), 4MB
__device__ float g_c[BATCH * ATT];     // prev_h@W_dec + b_dec + b_enc
__device__ float g_scores[NROWS];

// ---------------------------------------------------------------------------
__device__ __forceinline__ uint32_t smem_u32(const void* p) {
    uint32_t a;
    asm("{ .reg .u64 t; cvta.to.shared.u64 t, %1; cvt.u32.u64 %0, t; }"
        : "=r"(a) : "l"(p));
    return a;
}
__device__ __forceinline__ uint32_t f2tf32(float x) {
    uint32_t u;
    asm("cvt.rna.tf32.f32 %0, %1;" : "=r"(u) : "f"(x));
    return u;
}
__device__ __forceinline__ void cp_async16(uint32_t dst, const void* src) {
    asm volatile("cp.async.cg.shared.global [%0], [%1], 16;"
                 :: "r"(dst), "l"(src) : "memory");
}
__device__ __forceinline__ void cp_commit() {
    asm volatile("cp.async.commit_group;" ::: "memory");
}
template <int N>
__device__ __forceinline__ void cp_wait() {
    asm volatile("cp.async.wait_group %0;" :: "n"(N) : "memory");
}
__device__ __forceinline__ void mma8(float* c, const uint32_t* a, const uint32_t* b) {
    asm volatile(
        "mma.sync.aligned.m16n8k8.row.col.f32.tf32.tf32.f32 "
        "{%0,%1,%2,%3}, {%4,%5,%6,%7}, {%8,%9}, {%0,%1,%2,%3};\n"
        : "+f"(c[0]), "+f"(c[1]), "+f"(c[2]), "+f"(c[3])
        : "r"(a[0]), "r"(a[1]), "r"(a[2]), "r"(a[3]),
          "r"(b[0]), "r"(b[1]));
}

// ---------------------------------------------------------------------------
// Kernel 0: round W_enc to tf32 (RNA) + zero the score accumulator
// ---------------------------------------------------------------------------
__global__ void k_prep(const float* __restrict__ W_enc) {
    int i = blockIdx.x * 1024 + threadIdx.x;   // grid 1024 x 1024 == DIM*ATT
    g_Wenc_r[i] = __uint_as_float(f2tf32(W_enc[i]));
    if (i < NROWS) g_scores[i] = 0.f;
}

// ---------------------------------------------------------------------------
// Kernel 1: c[n,a] = b_enc[a] + b_dec[a] + prev_h[n,:] @ W_dec[:,a]
// ---------------------------------------------------------------------------
__global__ void __launch_bounds__(512)
k_compute_c(const float* __restrict__ prev_h,
            const float* __restrict__ W_dec,
            const float* __restrict__ b_enc,
            const float* __restrict__ b_dec) {
    __shared__ float sh[8][ATT];
    int nb = blockIdx.x * 8;
    int a = threadIdx.x;
#pragma unroll
    for (int i = 0; i < 8; i++) sh[i][a] = prev_h[(nb + i) * ATT + a];
    __syncthreads();

    float base = b_enc[a] + b_dec[a];
    float acc[8];
#pragma unroll
    for (int i = 0; i < 8; i++) acc[i] = base;
#pragma unroll 4
    for (int h = 0; h < ATT; h++) {
        float w = W_dec[h * ATT + a];
#pragma unroll
        for (int i = 0; i < 8; i++) acc[i] = fmaf(sh[i][h], w, acc[i]);
    }
#pragma unroll
    for (int i = 0; i < 8; i++) g_c[(nb + i) * ATT + a] = acc[i];
}

// ---------------------------------------------------------------------------
// Kernel 2: tf32 mma.sync GEMM (M=50176,N=512,K=2048), cp.async 3-stage pipe,
// fused epilogue scores[row] += sum_a relu(att1+c)*W_tot
// grid: (2 nTiles, 392 mTiles), 256 threads
// ---------------------------------------------------------------------------
__global__ void __launch_bounds__(THREADS, 1)
k_scores_mma(const float* __restrict__ feature,
             const float* __restrict__ W_tot) {
    extern __shared__ char dsm[];
    const uint32_t raw = smem_u32(dsm);
    const uint32_t base = (raw + 127u) & ~127u;
    char* alig = dsm + (base - raw);

    float* cs = (float*)(alig + OFF_CS);   // [2][BN]
    float* wt = (float*)(alig + OFF_WT);   // [BN]

    const int t = threadIdx.x;
    const int warp = t >> 5;
    const int lane = t & 31;
    const int g = lane >> 2;               // 0..7
    const int tig = lane & 3;              // 0..3
    const int warpm = warp >> 2;           // 0..1
    const int warpn = warp & 3;            // 0..3

    const int nTile = blockIdx.x;
    const int rowTile = blockIdx.y * BM;
    const int colTile = nTile * BN;

    const int n0 = rowTile / LSEQ;
    const int n1 = (n0 + 1 < BATCH) ? n0 + 1 : BATCH - 1;
    const int n1row = (n0 + 1) * LSEQ;

    cs[t]      = g_c[n0 * ATT + colTile + t];
    cs[BN + t] = g_c[n1 * ATT + colTile + t];
    wt[t]      = W_tot[colTile + t];

    // ---- loader: fill stage s with K-chunk it2 ----
    auto load_stage = [&](int it2, int s) {
        const int k0 = it2 * BK;
        const uint32_t dA = base + OFF_SA + (uint32_t)s * A_STAGE;
        const uint32_t dB = base + OFF_SB + (uint32_t)s * B_STAGE;
        // A: 128 rows x 8 x 16B = 1024 chunks, 4/thread
#pragma unroll
        for (int j = 0; j < 4; j++) {
            int idx = t + j * THREADS;
            int row = idx >> 3, c = idx & 7;
            const float* src = feature + (size_t)(rowTile + row) * DIM + k0 + c * 4;
            cp_async16(dA + (uint32_t)(row * (A_STRIDE * 4) + c * 16), src);
        }
        // B: 32 k-rows x 64 x 16B = 2048 chunks, 8/thread
#pragma unroll
        for (int j = 0; j < 8; j++) {
            int idx = t + j * THREADS;
            int kk = idx >> 6, c = idx & 63;
            const float* src = g_Wenc_r + (size_t)(k0 + kk) * ATT + colTile + c * 4;
            cp_async16(dB + (uint32_t)(kk * (B_STRIDE * 4) + c * 16), src);
        }
        cp_commit();
    };

    float acc[4][8][4];
#pragma unroll
    for (int mt = 0; mt < 4; mt++)
#pragma unroll
        for (int nt = 0; nt < 8; nt++)
#pragma unroll
            for (int r = 0; r < 4; r++) acc[mt][nt][r] = 0.f;

    load_stage(0, 0);
    load_stage(1, 1);

    for (int it = 0; it < NIT; it++) {
        if (it + 2 < NIT) cp_wait<1>(); else cp_wait<0>();
        __syncthreads();
        if (it + 2 < NIT) load_stage(it + 2, (it + 2) % 3);

        const int s = it % 3;
        const uint32_t* As = (const uint32_t*)(alig + OFF_SA + (uint32_t)s * A_STAGE);
        const uint32_t* Bs = (const uint32_t*)(alig + OFF_SB + (uint32_t)s * B_STAGE);

#pragma unroll
        for (int ks = 0; ks < 4; ks++) {
            uint32_t af[4][4];
#pragma unroll
            for (int mt = 0; mt < 4; mt++) {
                int r0 = warpm * 64 + mt * 16 + g;
                const uint32_t* p0 = As + r0 * A_STRIDE + ks * 8 + tig;
                af[mt][0] = p0[0];
                af[mt][1] = p0[8 * A_STRIDE];
                af[mt][2] = p0[4];
                af[mt][3] = p0[8 * A_STRIDE + 4];
            }
            uint32_t bf[8][2];
#pragma unroll
            for (int nt = 0; nt < 8; nt++) {
                int col = warpn * 64 + nt * 8 + g;
                const uint32_t* p = Bs + (ks * 8 + tig) * B_STRIDE + col;
                bf[nt][0] = p[0];
                bf[nt][1] = p[4 * B_STRIDE];
            }
#pragma unroll
            for (int mt = 0; mt < 4; mt++)
#pragma unroll
                for (int nt = 0; nt < 8; nt++)
                    mma8(acc[mt][nt], af[mt], bf[nt]);
        }
    }

    // ---- fused epilogue: relu(+c) dot W_tot, shfl-reduce, global atomic ----
#pragma unroll
    for (int mt = 0; mt < 4; mt++) {
        int rl0 = warpm * 64 + mt * 16 + g;
        int rl1 = rl0 + 8;
        int sel0 = (rowTile + rl0 >= n1row) ? 1 : 0;
        int sel1 = (rowTile + rl1 >= n1row) ? 1 : 0;
        const float* c0 = cs + sel0 * BN;
        const float* c1 = cs + sel1 * BN;

        float rs0 = 0.f, rs1 = 0.f;
#pragma unroll
        for (int nt = 0; nt < 8; nt++) {
            int col = warpn * 64 + nt * 8 + tig * 2;
            float w0 = wt[col], w1 = wt[col + 1];
            rs0 += fmaxf(acc[mt][nt][0] + c0[col], 0.f) * w0
                 + fmaxf(acc[mt][nt][1] + c0[col + 1], 0.f) * w1;
            rs1 += fmaxf(acc[mt][nt][2] + c1[col], 0.f) * w0
                 + fmaxf(acc[mt][nt][3] + c1[col + 1], 0.f) * w1;
        }
        rs0 += __shfl_xor_sync(0xffffffff, rs0, 1);
        rs0 += __shfl_xor_sync(0xffffffff, rs0, 2);
        rs1 += __shfl_xor_sync(0xffffffff, rs1, 1);
        rs1 += __shfl_xor_sync(0xffffffff, rs1, 2);
        if (tig == 0) {
            atomicAdd(&g_scores[rowTile + rl0], rs0);
            atomicAdd(&g_scores[rowTile + rl1], rs1);
        }
    }
}

// ---------------------------------------------------------------------------
// Kernel 3: softmax over L per batch (b_tot dropped: shift-invariant)
// ---------------------------------------------------------------------------
__global__ void k_softmax(float* __restrict__ alpha_out) {
    __shared__ float red[256];
    int n = blockIdx.x;
    int t = threadIdx.x;

    float v = (t < LSEQ) ? g_scores[n * LSEQ + t] : -1e30f;
    red[t] = v;
    __syncthreads();
    for (int s = 128; s > 0; s >>= 1) {
        if (t < s) red[t] = fmaxf(red[t], red[t + s]);
        __syncthreads();
    }
    float vmax = red[0];
    __syncthreads();

    float e = (t < LSEQ) ? __expf(v - vmax) : 0.f;
    red[t] = e;
    __syncthreads();
    for (int s = 128; s > 0; s >>= 1) {
        if (t < s) red[t] += red[t + s];
        __syncthreads();
    }
    float inv = 1.f / red[0];

    if (t < LSEQ) alpha_out[n * LSEQ + t] = e * inv;
}

// ---------------------------------------------------------------------------
// Kernel 4: weighted_feature[n,d] = sum_l alpha[n,l] * feature[n,l,d]
// ---------------------------------------------------------------------------
__global__ void k_weighted(const float* __restrict__ feature,
                           const float* __restrict__ alpha,
                           float* __restrict__ out) {
    __shared__ float sa[LSEQ];
    int n = blockIdx.x;
    int half = blockIdx.y;
    int t = threadIdx.x;
    if (t < LSEQ) sa[t] = alpha[n * LSEQ + t];
    __syncthreads();

    const float4* f = (const float4*)(feature + (size_t)n * LSEQ * DIM)
                      + half * 256 + t;
    float4 acc = make_float4(0.f, 0.f, 0.f, 0.f);
#pragma unroll 8
    for (int l = 0; l < LSEQ; l++) {
        float4 v = f[(size_t)l * (DIM / 4)];
        float al = sa[l];
        acc.x = fmaf(al, v.x, acc.x);
        acc.y = fmaf(al, v.y, acc.y);
        acc.z = fmaf(al, v.z, acc.z);
        acc.w = fmaf(al, v.w, acc.w);
    }
    ((float4*)(out + (size_t)n * DIM))[half * 256 + t] = acc;
}

// ---------------------------------------------------------------------------
extern "C" void kernel_launch(void* const* d_in, const int* in_sizes, int n_in,
                              void* d_out, int out_size) {
    const float* feature = (const float*)d_in[0];
    const float* prev_h  = (const float*)d_in[1];
    const float* W_enc   = (const float*)d_in[2];
    const float* b_enc   = (const float*)d_in[3];
    const float* W_dec   = (const float*)d_in[4];
    const float* b_dec   = (const float*)d_in[5];
    const float* W_tot   = (const float*)d_in[6];
    // d_in[7] = b_tot: softmax shift-invariant -> unused

    float* out   = (float*)d_out;
    float* wf    = out;                        // (BATCH, DIM)
    float* alpha = out + (size_t)BATCH * DIM;  // (BATCH, LSEQ)

    cudaFuncSetAttribute(k_scores_mma,
                         cudaFuncAttributeMaxDynamicSharedMemorySize, SMEM_BYTES);

    k_prep<<<1024, 1024>>>(W_enc);
    k_compute_c<<<BATCH / 8, 512>>>(prev_h, W_dec, b_enc, b_dec);
    k_scores_mma<<<dim3(2, NROWS / BM), THREADS, SMEM_BYTES>>>(feature, W_tot);
    k_softmax<<<BATCH, 256>>>(alpha);
    k_weighted<<<dim3(BATCH, 2), 256>>>(feature, alpha, wf);
}

// round 5
// speedup vs baseline: 4.6899x; 1.0009x over previous
#include <cuda_runtime.h>
#include <cstdint>

#define BATCH 256
#define LSEQ  196
#define DIM   2048
#define ATT   512
#define NROWS (BATCH * LSEQ)   // 50176 = 392 * 128

// GEMM tiling
#define BM 128
#define BN 256
#define BK 32
#define NIT (DIM / BK)         // 64
#define THREADS 256            // 8 warps: 2 (m) x 4 (n), warp tile 64x64

#define A_STRIDE 36            // floats per A row (32 + 4 pad)
#define B_STRIDE 264           // floats per B k-row (256 + 8 pad)
#define A_STAGE (BM * A_STRIDE * 4)   // 18432 B
#define B_STAGE (BK * B_STRIDE * 4)   // 33792 B
#define OFF_SA 0u
#define OFF_SB (3u * A_STAGE)                 // 55296
#define OFF_CS (OFF_SB + 3u * B_STAGE)        // 156672  float[2][BN]
#define OFF_WT (OFF_CS + 2u * BN * 4u)        // 158720  float[BN]
#define SMEM_BYTES (OFF_WT + BN * 4u + 256u)  // ~160 KB

// Scratch globals (no allocation allowed)
__device__ float g_Wenc_r[DIM * ATT];  // W_enc rounded to tf32 (RNA), 4MB
__device__ float g_c[BATCH * ATT];     // prev_h@W_dec + b_dec + b_enc
__device__ float g_scores[NROWS];

// ---------------------------------------------------------------------------
__device__ __forceinline__ uint32_t smem_u32(const void* p) {
    uint32_t a;
    asm("{ .reg .u64 t; cvta.to.shared.u64 t, %1; cvt.u32.u64 %0, t; }"
        : "=r"(a) : "l"(p));
    return a;
}
__device__ __forceinline__ uint32_t f2tf32(float x) {
    uint32_t u;
    asm("cvt.rna.tf32.f32 %0, %1;" : "=r"(u) : "f"(x));
    return u;
}
__device__ __forceinline__ void cp_async16(uint32_t dst, const void* src) {
    asm volatile("cp.async.cg.shared.global [%0], [%1], 16;"
                 :: "r"(dst), "l"(src) : "memory");
}
__device__ __forceinline__ void cp_commit() {
    asm volatile("cp.async.commit_group;" ::: "memory");
}
template <int N>
__device__ __forceinline__ void cp_wait() {
    asm volatile("cp.async.wait_group %0;" :: "n"(N) : "memory");
}
__device__ __forceinline__ void mma8(float* c, const uint32_t* a, const uint32_t* b) {
    asm volatile(
        "mma.sync.aligned.m16n8k8.row.col.f32.tf32.tf32.f32 "
        "{%0,%1,%2,%3}, {%4,%5,%6,%7}, {%8,%9}, {%0,%1,%2,%3};\n"
        : "+f"(c[0]), "+f"(c[1]), "+f"(c[2]), "+f"(c[3])
        : "r"(a[0]), "r"(a[1]), "r"(a[2]), "r"(a[3]),
          "r"(b[0]), "r"(b[1]));
}

// ---------------------------------------------------------------------------
// Kernel 0: round W_enc to tf32 (RNA) + zero the score accumulator
// ---------------------------------------------------------------------------
__global__ void k_prep(const float* __restrict__ W_enc) {
    int i = blockIdx.x * 1024 + threadIdx.x;   // grid 1024 x 1024 == DIM*ATT
    g_Wenc_r[i] = __uint_as_float(f2tf32(W_enc[i]));
    if (i < NROWS) g_scores[i] = 0.f;
}

// ---------------------------------------------------------------------------
// Kernel 1: c[n,a] = b_enc[a] + b_dec[a] + prev_h[n,:] @ W_dec[:,a]
// ---------------------------------------------------------------------------
__global__ void __launch_bounds__(512)
k_compute_c(const float* __restrict__ prev_h,
            const float* __restrict__ W_dec,
            const float* __restrict__ b_enc,
            const float* __restrict__ b_dec) {
    __shared__ float sh[8][ATT];
    int nb = blockIdx.x * 8;
    int a = threadIdx.x;
#pragma unroll
    for (int i = 0; i < 8; i++) sh[i][a] = prev_h[(nb + i) * ATT + a];
    __syncthreads();

    float base = b_enc[a] + b_dec[a];
    float acc[8];
#pragma unroll
    for (int i = 0; i < 8; i++) acc[i] = base;
#pragma unroll 4
    for (int h = 0; h < ATT; h++) {
        float w = W_dec[h * ATT + a];
#pragma unroll
        for (int i = 0; i < 8; i++) acc[i] = fmaf(sh[i][h], w, acc[i]);
    }
#pragma unroll
    for (int i = 0; i < 8; i++) g_c[(nb + i) * ATT + a] = acc[i];
}

// ---------------------------------------------------------------------------
// Kernel 2: tf32 mma.sync GEMM (M=50176,N=512,K=2048), cp.async 3-stage pipe,
// fused epilogue scores[row] += sum_a relu(att1+c)*W_tot
// grid: (2 nTiles, 392 mTiles), 256 threads
// ---------------------------------------------------------------------------
__global__ void __launch_bounds__(THREADS, 1)
k_scores_mma(const float* __restrict__ feature,
             const float* __restrict__ W_tot) {
    extern __shared__ char dsm[];
    const uint32_t raw = smem_u32(dsm);
    const uint32_t base = (raw + 127u) & ~127u;
    char* alig = dsm + (base - raw);

    float* cs = (float*)(alig + OFF_CS);   // [2][BN]
    float* wt = (float*)(alig + OFF_WT);   // [BN]

    const int t = threadIdx.x;
    const int warp = t >> 5;
    const int lane = t & 31;
    const int g = lane >> 2;               // 0..7
    const int tig = lane & 3;              // 0..3
    const int warpm = warp >> 2;           // 0..1
    const int warpn = warp & 3;            // 0..3

    const int nTile = blockIdx.x;
    const int rowTile = blockIdx.y * BM;
    const int colTile = nTile * BN;

    const int n0 = rowTile / LSEQ;
    const int n1 = (n0 + 1 < BATCH) ? n0 + 1 : BATCH - 1;
    const int n1row = (n0 + 1) * LSEQ;

    cs[t]      = g_c[n0 * ATT + colTile + t];
    cs[BN + t] = g_c[n1 * ATT + colTile + t];
    wt[t]      = W_tot[colTile + t];

    // ---- loader: fill stage s with K-chunk it2 ----
    auto load_stage = [&](int it2, int s) {
        const int k0 = it2 * BK;
        const uint32_t dA = base + OFF_SA + (uint32_t)s * A_STAGE;
        const uint32_t dB = base + OFF_SB + (uint32_t)s * B_STAGE;
        // A: 128 rows x 8 x 16B = 1024 chunks, 4/thread
#pragma unroll
        for (int j = 0; j < 4; j++) {
            int idx = t + j * THREADS;
            int row = idx >> 3, c = idx & 7;
            const float* src = feature + (size_t)(rowTile + row) * DIM + k0 + c * 4;
            cp_async16(dA + (uint32_t)(row * (A_STRIDE * 4) + c * 16), src);
        }
        // B: 32 k-rows x 64 x 16B = 2048 chunks, 8/thread
#pragma unroll
        for (int j = 0; j < 8; j++) {
            int idx = t + j * THREADS;
            int kk = idx >> 6, c = idx & 63;
            const float* src = g_Wenc_r + (size_t)(k0 + kk) * ATT + colTile + c * 4;
            cp_async16(dB + (uint32_t)(kk * (B_STRIDE * 4) + c * 16), src);
        }
        cp_commit();
    };

    float acc[4][8][4];
#pragma unroll
    for (int mt = 0; mt < 4; mt++)
#pragma unroll
        for (int nt = 0; nt < 8; nt++)
#pragma unroll
            for (int r = 0; r < 4; r++) acc[mt][nt][r] = 0.f;

    load_stage(0, 0);
    load_stage(1, 1);

    for (int it = 0; it < NIT; it++) {
        if (it + 2 < NIT) cp_wait<1>(); else cp_wait<0>();
        __syncthreads();
        if (it + 2 < NIT) load_stage(it + 2, (it + 2) % 3);

        const int s = it % 3;
        const uint32_t* As = (const uint32_t*)(alig + OFF_SA + (uint32_t)s * A_STAGE);
        const uint32_t* Bs = (const uint32_t*)(alig + OFF_SB + (uint32_t)s * B_STAGE);

#pragma unroll
        for (int ks = 0; ks < 4; ks++) {
            uint32_t af[4][4];
#pragma unroll
            for (int mt = 0; mt < 4; mt++) {
                int r0 = warpm * 64 + mt * 16 + g;
                const uint32_t* p0 = As + r0 * A_STRIDE + ks * 8 + tig;
                af[mt][0] = p0[0];
                af[mt][1] = p0[8 * A_STRIDE];
                af[mt][2] = p0[4];
                af[mt][3] = p0[8 * A_STRIDE + 4];
            }
            uint32_t bf[8][2];
#pragma unroll
            for (int nt = 0; nt < 8; nt++) {
                int col = warpn * 64 + nt * 8 + g;
                const uint32_t* p = Bs + (ks * 8 + tig) * B_STRIDE + col;
                bf[nt][0] = p[0];
                bf[nt][1] = p[4 * B_STRIDE];
            }
#pragma unroll
            for (int mt = 0; mt < 4; mt++)
#pragma unroll
                for (int nt = 0; nt < 8; nt++)
                    mma8(acc[mt][nt], af[mt], bf[nt]);
        }
    }

    // ---- fused epilogue: relu(+c) dot W_tot, shfl-reduce, global atomic ----
#pragma unroll
    for (int mt = 0; mt < 4; mt++) {
        int rl0 = warpm * 64 + mt * 16 + g;
        int rl1 = rl0 + 8;
        int sel0 = (rowTile + rl0 >= n1row) ? 1 : 0;
        int sel1 = (rowTile + rl1 >= n1row) ? 1 : 0;
        const float* c0 = cs + sel0 * BN;
        const float* c1 = cs + sel1 * BN;

        float rs0 = 0.f, rs1 = 0.f;
#pragma unroll
        for (int nt = 0; nt < 8; nt++) {
            int col = warpn * 64 + nt * 8 + tig * 2;
            float w0 = wt[col], w1 = wt[col + 1];
            rs0 += fmaxf(acc[mt][nt][0] + c0[col], 0.f) * w0
                 + fmaxf(acc[mt][nt][1] + c0[col + 1], 0.f) * w1;
            rs1 += fmaxf(acc[mt][nt][2] + c1[col], 0.f) * w0
                 + fmaxf(acc[mt][nt][3] + c1[col + 1], 0.f) * w1;
        }
        rs0 += __shfl_xor_sync(0xffffffff, rs0, 1);
        rs0 += __shfl_xor_sync(0xffffffff, rs0, 2);
        rs1 += __shfl_xor_sync(0xffffffff, rs1, 1);
        rs1 += __shfl_xor_sync(0xffffffff, rs1, 2);
        if (tig == 0) {
            atomicAdd(&g_scores[rowTile + rl0], rs0);
            atomicAdd(&g_scores[rowTile + rl1], rs1);
        }
    }
}

// ---------------------------------------------------------------------------
// Kernel 3: softmax over L per batch (b_tot dropped: shift-invariant)
// ---------------------------------------------------------------------------
__global__ void k_softmax(float* __restrict__ alpha_out) {
    __shared__ float red[256];
    int n = blockIdx.x;
    int t = threadIdx.x;

    float v = (t < LSEQ) ? g_scores[n * LSEQ + t] : -1e30f;
    red[t] = v;
    __syncthreads();
    for (int s = 128; s > 0; s >>= 1) {
        if (t < s) red[t] = fmaxf(red[t], red[t + s]);
        __syncthreads();
    }
    float vmax = red[0];
    __syncthreads();

    float e = (t < LSEQ) ? __expf(v - vmax) : 0.f;
    red[t] = e;
    __syncthreads();
    for (int s = 128; s > 0; s >>= 1) {
        if (t < s) red[t] += red[t + s];
        __syncthreads();
    }
    float inv = 1.f / red[0];

    if (t < LSEQ) alpha_out[n * LSEQ + t] = e * inv;
}

// ---------------------------------------------------------------------------
// Kernel 4: weighted_feature[n,d] = sum_l alpha[n,l] * feature[n,l,d]
// ---------------------------------------------------------------------------
__global__ void k_weighted(const float* __restrict__ feature,
                           const float* __restrict__ alpha,
                           float* __restrict__ out) {
    __shared__ float sa[LSEQ];
    int n = blockIdx.x;
    int half = blockIdx.y;
    int t = threadIdx.x;
    if (t < LSEQ) sa[t] = alpha[n * LSEQ + t];
    __syncthreads();

    const float4* f = (const float4*)(feature + (size_t)n * LSEQ * DIM)
                      + half * 256 + t;
    float4 acc = make_float4(0.f, 0.f, 0.f, 0.f);
#pragma unroll 8
    for (int l = 0; l < LSEQ; l++) {
        float4 v = f[(size_t)l * (DIM / 4)];
        float al = sa[l];
        acc.x = fmaf(al, v.x, acc.x);
        acc.y = fmaf(al, v.y, acc.y);
        acc.z = fmaf(al, v.z, acc.z);
        acc.w = fmaf(al, v.w, acc.w);
    }
    ((float4*)(out + (size_t)n * DIM))[half * 256 + t] = acc;
}

// ---------------------------------------------------------------------------
extern "C" void kernel_launch(void* const* d_in, const int* in_sizes, int n_in,
                              void* d_out, int out_size) {
    const float* feature = (const float*)d_in[0];
    const float* prev_h  = (const float*)d_in[1];
    const float* W_enc   = (const float*)d_in[2];
    const float* b_enc   = (const float*)d_in[3];
    const float* W_dec   = (const float*)d_in[4];
    const float* b_dec   = (const float*)d_in[5];
    const float* W_tot   = (const float*)d_in[6];
    // d_in[7] = b_tot: softmax shift-invariant -> unused

    float* out   = (float*)d_out;
    float* wf    = out;                        // (BATCH, DIM)
    float* alpha = out + (size_t)BATCH * DIM;  // (BATCH, LSEQ)

    cudaFuncSetAttribute(k_scores_mma,
                         cudaFuncAttributeMaxDynamicSharedMemorySize, SMEM_BYTES);

    k_prep<<<1024, 1024>>>(W_enc);
    k_compute_c<<<BATCH / 8, 512>>>(prev_h, W_dec, b_enc, b_dec);
    k_scores_mma<<<dim3(2, NROWS / BM), THREADS, SMEM_BYTES>>>(feature, W_tot);
    k_softmax<<<BATCH, 256>>>(alpha);
    k_weighted<<<dim3(BATCH, 2), 256>>>(feature, alpha, wf);
}